// round 1
// baseline (speedup 1.0000x reference)
#include <cuda_runtime.h>

// Problem constants
#define T_STEPS 1024
#define BATCH   32
#define INDIM   512
#define HDIM    512
#define G4      2048            // 4*H
#define NCTA    128             // persistent scan CTAs (all co-resident on 148 SMs)

// Scratch: gates_x stored as [t][n][b] (n-major, b-minor) so the scan kernel
// reads coalesced 32-float runs per gate row.
__device__ float g_gates[(size_t)T_STEPS * G4 * BATCH];  // 256 MB
// Double-buffered recurrent hidden state, layout [j*32 + b] (j-major, b-minor)
__device__ float g_h[2][HDIM * BATCH];
// Software grid barrier state
__device__ unsigned g_bar_count = 0;
__device__ unsigned g_bar_gen   = 0;

// ---------------------------------------------------------------------------
// Phase 1: gates_x GEMM.  C[m][n] = sum_k input[m][k]*W_ih[n][k] + bias[n]
// M = 32768 (t*32+b), N = 2048, K = 512.  64x64 tile, 256 threads, 4x4/thread.
// Tiles stored transposed [k][mn] in smem for conflict-free inner loads.
// ---------------------------------------------------------------------------
__global__ __launch_bounds__(256, 2) void gemm_x_kernel(
    const float* __restrict__ A,     // input  [M, 512]
    const float* __restrict__ W,     // W_ih   [2048, 512]
    const float* __restrict__ b_ih,
    const float* __restrict__ b_hh)
{
    __shared__ float As[2][16][68];
    __shared__ float Bs[2][16][68];

    const int tid = threadIdx.x;
    const int tx  = tid & 15;        // n-tile lane
    const int ty  = tid >> 4;        // m-tile lane
    const int m0  = blockIdx.y << 6;
    const int n0  = blockIdx.x << 6;

    // Global load mapping: each thread one float4 per tile
    const int lm = tid >> 2;             // 0..63
    const int lk = (tid & 3) << 2;       // 0,4,8,12
    const float* Ap = A + (size_t)(m0 + lm) * INDIM + lk;
    const float* Wp = W + (size_t)(n0 + lm) * INDIM + lk;

    float acc[4][4];
#pragma unroll
    for (int i = 0; i < 4; i++)
#pragma unroll
        for (int j = 0; j < 4; j++) acc[i][j] = 0.f;

    // prologue: tile 0
    float4 a4 = *(const float4*)Ap;
    float4 b4 = *(const float4*)Wp;
    As[0][lk + 0][lm] = a4.x; As[0][lk + 1][lm] = a4.y;
    As[0][lk + 2][lm] = a4.z; As[0][lk + 3][lm] = a4.w;
    Bs[0][lk + 0][lm] = b4.x; Bs[0][lk + 1][lm] = b4.y;
    Bs[0][lk + 2][lm] = b4.z; Bs[0][lk + 3][lm] = b4.w;
    __syncthreads();

    int buf = 0;
    for (int kt = 16; kt <= INDIM; kt += 16) {
        const bool more = (kt < INDIM);
        float4 na, nb;
        if (more) {
            na = *(const float4*)(Ap + kt);
            nb = *(const float4*)(Wp + kt);
        }
#pragma unroll
        for (int k = 0; k < 16; k++) {
            float av[4], bv[4];
#pragma unroll
            for (int i = 0; i < 4; i++) av[i] = As[buf][k][ty + (i << 4)];
#pragma unroll
            for (int i = 0; i < 4; i++) bv[i] = Bs[buf][k][tx + (i << 4)];
#pragma unroll
            for (int i = 0; i < 4; i++)
#pragma unroll
                for (int j = 0; j < 4; j++)
                    acc[i][j] = fmaf(av[i], bv[j], acc[i][j]);
        }
        if (more) {
            const int nb_ = buf ^ 1;
            As[nb_][lk + 0][lm] = na.x; As[nb_][lk + 1][lm] = na.y;
            As[nb_][lk + 2][lm] = na.z; As[nb_][lk + 3][lm] = na.w;
            Bs[nb_][lk + 0][lm] = nb.x; Bs[nb_][lk + 1][lm] = nb.y;
            Bs[nb_][lk + 2][lm] = nb.z; Bs[nb_][lk + 3][lm] = nb.w;
        }
        __syncthreads();
        buf ^= 1;
    }

    // Epilogue: add bias, store to [t][n][b] layout
#pragma unroll
    for (int jj = 0; jj < 4; jj++) {
        const int n = n0 + tx + (jj << 4);
        const float bias = b_ih[n] + b_hh[n];
#pragma unroll
        for (int i = 0; i < 4; i++) {
            const int m = m0 + ty + (i << 4);
            g_gates[(size_t)(m >> 5) * (G4 * BATCH) + (size_t)n * BATCH + (m & 31)]
                = acc[i][jj] + bias;
        }
    }
}

// ---------------------------------------------------------------------------
// Software grid barrier (all NCTA CTAs are co-resident: 1 CTA/SM, 128 <= 148)
// ---------------------------------------------------------------------------
__device__ __forceinline__ void grid_sync()
{
    __syncthreads();
    if (threadIdx.x == 0) {
        const unsigned gen = *((volatile unsigned*)&g_bar_gen);
        __threadfence();
        const unsigned old = atomicAdd(&g_bar_count, 1u);
        if (old == (unsigned)gridDim.x - 1u) {
            atomicExch(&g_bar_count, 0u);
            __threadfence();
            atomicAdd(&g_bar_gen, 1u);
        } else {
            while (*((volatile unsigned*)&g_bar_gen) == gen) { }
        }
    }
    __syncthreads();
}

// ---------------------------------------------------------------------------
// Phase 2: persistent recurrent scan.
// CTA s owns h-units j in [4s, 4s+4).  Gate rows {g*512 + j} (16 rows) of W_hh
// live in smem for the whole kernel (transposed [k][rr]).  c stays in regs.
// Per step: all-gather h into smem (transposed [k][b]), 8-way K-split GEMM
// with 4x4 register tiles, swizzled smem reduction, activations, grid barrier.
// ---------------------------------------------------------------------------
__global__ __launch_bounds__(256, 1) void lstm_scan_kernel(
    const float* __restrict__ h0,
    const float* __restrict__ c0,
    const float* __restrict__ Whh,   // [2048, 512]
    float* __restrict__ out)         // d_out: [T,B,H] ++ h_f[B,H] ++ c_f[B,H]
{
    extern __shared__ float sm[];
    float* hshT = sm;                       // [512][32]   h transposed
    float* WshT = hshT + HDIM * BATCH;      // [512][16]   W slice transposed
    float* red  = WshT + HDIM * 16;         // [8][512]    K-group partials
    float* hn   = red  + 8 * 512;           // [4][32]     h_new staging

    const int tid = threadIdx.x;
    const int j0  = blockIdx.x << 2;        // first owned h-unit

    // Load W_hh slice: WshT[k*16 + rr], rr = u + 4*g  ->  global row g*512+j0+u
    for (int idx = tid; idx < 16 * HDIM; idx += 256) {
        const int rr = idx >> 9;            // 0..15
        const int k  = idx & 511;
        const int g  = rr >> 2, u = rr & 3;
        WshT[k * 16 + rr] = Whh[(size_t)(g * HDIM + j0 + u) * HDIM + k];
    }

    // GEMM lane mapping
    const int kg   = tid >> 5;              // k-group 0..7 (64 k each)
    const int lane = tid & 31;
    const int tb   = lane & 7;              // b tiles: tb + 8*i
    const int tr   = lane >> 3;             // r tiles: tr + 4*ii  (rr = u + 4*g)

    // Activation lane mapping (tid < 128): (b, u)
    const int bb = tid & 31;
    const int uu = tid >> 5;                // 0..3 for tid<128

    float c_reg = 0.f;
    if (tid < 128) c_reg = c0[bb * HDIM + j0 + uu];

    float* hf = out + (size_t)T_STEPS * BATCH * HDIM;
    float* cf = hf + BATCH * HDIM;

    for (int t = 0; t < T_STEPS; t++) {
        // ---- all-gather h into hshT [k][b] ----
        if (t == 0) {
            for (int idx = tid; idx < HDIM * BATCH; idx += 256) {
                const int k = idx >> 5, b = idx & 31;
                hshT[idx] = h0[b * HDIM + k];
            }
        } else {
            const float4* src = (const float4*)g_h[t & 1];
            float4* dst = (float4*)hshT;
#pragma unroll
            for (int i = 0; i < 16; i++) dst[tid + i * 256] = src[tid + i * 256];
        }

        // prefetch gates_x for this step (independent of h)
        float gxv[4] = {0.f, 0.f, 0.f, 0.f};
        if (tid < 128) {
#pragma unroll
            for (int g = 0; g < 4; g++)
                gxv[g] = g_gates[(size_t)t * (G4 * BATCH)
                                 + (size_t)(g * HDIM + j0 + uu) * BATCH + bb];
        }
        __syncthreads();

        // ---- K-split mini-GEMM: acc[i][ii] over k in [kg*64, kg*64+64) ----
        float acc[4][4];
#pragma unroll
        for (int i = 0; i < 4; i++)
#pragma unroll
            for (int j = 0; j < 4; j++) acc[i][j] = 0.f;

        const int kbeg = kg << 6;
#pragma unroll 4
        for (int k = kbeg; k < kbeg + 64; k++) {
            float hv[4], wv[4];
#pragma unroll
            for (int i = 0; i < 4; i++) hv[i] = hshT[k * 32 + tb + (i << 3)];
#pragma unroll
            for (int i = 0; i < 4; i++) wv[i] = WshT[k * 16 + tr + (i << 2)];
#pragma unroll
            for (int i = 0; i < 4; i++)
#pragma unroll
                for (int ii = 0; ii < 4; ii++)
                    acc[i][ii] = fmaf(hv[i], wv[ii], acc[i][ii]);
        }

        // ---- store partials (bank-swizzled: bcol = (b + 8r) & 31) ----
#pragma unroll
        for (int ii = 0; ii < 4; ii++) {
            const int r = tr + (ii << 2);
#pragma unroll
            for (int i = 0; i < 4; i++) {
                const int b = tb + (i << 3);
                red[kg * 512 + r * 32 + ((b + (r << 3)) & 31)] = acc[i][ii];
            }
        }
        __syncthreads();

        // ---- reduce + activations (tid < 128: one (b, u) cell each) ----
        if (tid < 128) {
            float s[4];
#pragma unroll
            for (int g = 0; g < 4; g++) {
                const int r   = (g << 2) + uu;
                const int col = r * 32 + ((bb + (r << 3)) & 31);
                float v = gxv[g];
#pragma unroll
                for (int kk = 0; kk < 8; kk++) v += red[kk * 512 + col];
                s[g] = v;
            }
            const float ig = 1.f / (1.f + expf(-s[0]));
            const float fg = 1.f / (1.f + expf(-s[1]));
            const float gg = tanhf(s[2]);
            const float og = 1.f / (1.f + expf(-s[3]));
            c_reg = fg * c_reg + ig * gg;
            const float hnew = og * tanhf(c_reg);

            g_h[(t + 1) & 1][(j0 + uu) * 32 + bb] = hnew;   // coalesced
            hn[uu * 32 + bb] = hnew;
            if (t == T_STEPS - 1) {
                hf[bb * HDIM + j0 + uu] = hnew;
                cf[bb * HDIM + j0 + uu] = c_reg;
            }
        }
        __syncthreads();

        // ---- coalesced-ish float4 output store: out[t][b][j0..j0+3] ----
        if (tid < 32) {
            const float4 o4 = make_float4(hn[tid], hn[32 + tid],
                                          hn[64 + tid], hn[96 + tid]);
            *(float4*)(out + (size_t)t * (BATCH * HDIM) + tid * HDIM + j0) = o4;
        }

        grid_sync();
    }
}

// ---------------------------------------------------------------------------
extern "C" void kernel_launch(void* const* d_in, const int* in_sizes, int n_in,
                              void* d_out, int out_size)
{
    const float* input = (const float*)d_in[0];   // [T,B,I]
    const float* h0    = (const float*)d_in[1];   // [B,H]
    const float* c0    = (const float*)d_in[2];   // [B,H]
    const float* W_ih  = (const float*)d_in[3];   // [4H,I]
    const float* W_hh  = (const float*)d_in[4];   // [4H,H]
    const float* b_ih  = (const float*)d_in[5];   // [4H]
    const float* b_hh  = (const float*)d_in[6];   // [4H]
    float* out = (float*)d_out;

    dim3 g1(G4 / 64, (T_STEPS * BATCH) / 64);     // (32, 512)
    gemm_x_kernel<<<g1, 256>>>(input, W_ih, b_ih, b_hh);

    const int smem_bytes = (HDIM * BATCH + HDIM * 16 + 8 * 512 + 4 * 32)
                           * (int)sizeof(float);  // 115200 B
    cudaFuncSetAttribute(lstm_scan_kernel,
                         cudaFuncAttributeMaxDynamicSharedMemorySize, smem_bytes);
    lstm_scan_kernel<<<NCTA, 256, smem_bytes>>>(h0, c0, W_hh, out);
}

// round 3
// speedup vs baseline: 1.2925x; 1.2925x over previous
#include <cuda_runtime.h>
#include <cstdint>

// Problem constants
#define T_STEPS 1024
#define BATCH   32
#define INDIM   512
#define HDIM    512
#define G4      2048            // 4*H
#define NCTA    128             // persistent scan CTAs

// Scratch: gates_x stored as [t][n][b] (n-major, b-minor)
__device__ float g_gates[(size_t)T_STEPS * G4 * BATCH];  // 256 MB
// Double-buffered recurrent hidden state, layout [j*32 + b] (full fp32)
__device__ float g_h[2][HDIM * BATCH];
// Software grid barrier state
__device__ unsigned g_bar_count = 0;
__device__ unsigned g_bar_gen   = 0;

// ---------------------------------------------------------------------------
// tf32 helpers (3xTF32 scheme: x*y ~= xb*yb + xs*yb + xb*ys)
// ---------------------------------------------------------------------------
__device__ __forceinline__ unsigned f2tf(float x) {
    unsigned r;
    asm("cvt.rna.tf32.f32 %0, %1;" : "=r"(r) : "f"(x));
    return r;
}
__device__ __forceinline__ float f2tf_f(float x) { return __uint_as_float(f2tf(x)); }

__device__ __forceinline__ void mma_tf32(float c[4],
                                         unsigned a0, unsigned a1, unsigned a2, unsigned a3,
                                         unsigned b0, unsigned b1) {
    asm volatile(
        "mma.sync.aligned.m16n8k8.row.col.f32.tf32.tf32.f32 "
        "{%0,%1,%2,%3}, {%4,%5,%6,%7}, {%8,%9}, {%0,%1,%2,%3};"
        : "+f"(c[0]), "+f"(c[1]), "+f"(c[2]), "+f"(c[3])
        : "r"(a0), "r"(a1), "r"(a2), "r"(a3), "r"(b0), "r"(b1));
}

// ---------------------------------------------------------------------------
// Phase 1: gates_x GEMM (3xTF32).  C[m][n] = sum_k A[m][k]*W[n][k] + bias[n]
// M=32768, N=2048, K=512.  128x64 tile / CTA, 256 thr, 8 warps = 2m x 4n of
// (4 m16 x 2 n8) mma tiles.  K chunks of 16, double-buffered smem with
// big/small split.  Row stride 20 -> conflict-free fragment LDS.
// ---------------------------------------------------------------------------
#define AST 20
#define P1_ABUF (128 * AST)
#define P1_BBUF (64 * AST)
#define P1_STRIDE (2 * P1_ABUF + 2 * P1_BBUF)   // per double-buffer slot

__device__ __forceinline__ void sts4split(float* pb, float* ps, float4 v) {
    const float bx = f2tf_f(v.x), by = f2tf_f(v.y);
    const float bz = f2tf_f(v.z), bw = f2tf_f(v.w);
    *(float4*)pb = make_float4(bx, by, bz, bw);
    *(float4*)ps = make_float4(f2tf_f(v.x - bx), f2tf_f(v.y - by),
                               f2tf_f(v.z - bz), f2tf_f(v.w - bw));
}

__global__ __launch_bounds__(256) void gemm_x_kernel(
    const float* __restrict__ A,     // input  [32768, 512]
    const float* __restrict__ W,     // W_ih   [2048, 512]
    const float* __restrict__ b_ih,
    const float* __restrict__ b_hh)
{
    extern __shared__ float sm1[];
    // layout per buffer slot: Ab | As | Bb | Bs

    const int tid  = threadIdx.x;
    const int w    = tid >> 5;
    const int lane = tid & 31;
    const int g8   = lane >> 2;      // groupID
    const int q4   = lane & 3;       // threadID_in_group
    const int wm   = w >> 2;         // 0..1 : which 64 rows
    const int wn   = w & 3;          // 0..3 : which 16 cols
    const int m0   = blockIdx.y << 7;
    const int n0   = blockIdx.x << 6;

    const int lr  = tid >> 2;            // 0..63
    const int lkq = (tid & 3) << 2;      // 0,4,8,12
    const float* Ap = A + (size_t)(m0 + lr) * INDIM + lkq;
    const float* Wp = W + (size_t)(n0 + lr) * INDIM + lkq;

    float acc[4][2][4];
#pragma unroll
    for (int mt = 0; mt < 4; mt++)
#pragma unroll
        for (int nt = 0; nt < 2; nt++)
#pragma unroll
            for (int e = 0; e < 4; e++) acc[mt][nt][e] = 0.f;

    // preload chunk 0
    {
        float* Ab = sm1;                float* As = sm1 + P1_ABUF;
        float* Bb = As + P1_ABUF;       float* Bs = Bb + P1_BBUF;
        sts4split(&Ab[lr * AST + lkq],        &As[lr * AST + lkq],        *(const float4*)Ap);
        sts4split(&Ab[(lr + 64) * AST + lkq], &As[(lr + 64) * AST + lkq], *(const float4*)(Ap + 64 * INDIM));
        sts4split(&Bb[lr * AST + lkq],        &Bs[lr * AST + lkq],        *(const float4*)Wp);
    }
    __syncthreads();

    int buf = 0;
    for (int kc = 0; kc < INDIM; kc += 16) {
        const bool more = (kc + 16 < INDIM);
        float4 na0, na1, nb0;
        if (more) {
            na0 = *(const float4*)(Ap + kc + 16);
            na1 = *(const float4*)(Ap + 64 * INDIM + kc + 16);
            nb0 = *(const float4*)(Wp + kc + 16);
        }
        const float* Ab = sm1 + buf * P1_STRIDE;
        const float* As = Ab + P1_ABUF;
        const float* Bb = As + P1_ABUF;
        const float* Bs = Bb + P1_BBUF;
#pragma unroll
        for (int kt = 0; kt < 16; kt += 8) {
            unsigned aRb[4][4], aRs[4][4], bRb[2][2], bRs[2][2];
#pragma unroll
            for (int mt = 0; mt < 4; mt++) {
                const int off = (wm * 64 + mt * 16 + g8) * AST + kt + q4;
                aRb[mt][0] = __float_as_uint(Ab[off]);
                aRb[mt][1] = __float_as_uint(Ab[off + 8 * AST]);
                aRb[mt][2] = __float_as_uint(Ab[off + 4]);
                aRb[mt][3] = __float_as_uint(Ab[off + 8 * AST + 4]);
                aRs[mt][0] = __float_as_uint(As[off]);
                aRs[mt][1] = __float_as_uint(As[off + 8 * AST]);
                aRs[mt][2] = __float_as_uint(As[off + 4]);
                aRs[mt][3] = __float_as_uint(As[off + 8 * AST + 4]);
            }
#pragma unroll
            for (int nt = 0; nt < 2; nt++) {
                const int off = (wn * 16 + nt * 8 + g8) * AST + kt + q4;
                bRb[nt][0] = __float_as_uint(Bb[off]);
                bRb[nt][1] = __float_as_uint(Bb[off + 4]);
                bRs[nt][0] = __float_as_uint(Bs[off]);
                bRs[nt][1] = __float_as_uint(Bs[off + 4]);
            }
#pragma unroll
            for (int mt = 0; mt < 4; mt++)
#pragma unroll
                for (int nt = 0; nt < 2; nt++) {
                    mma_tf32(acc[mt][nt], aRb[mt][0], aRb[mt][1], aRb[mt][2], aRb[mt][3],
                             bRb[nt][0], bRb[nt][1]);
                    mma_tf32(acc[mt][nt], aRs[mt][0], aRs[mt][1], aRs[mt][2], aRs[mt][3],
                             bRb[nt][0], bRb[nt][1]);
                    mma_tf32(acc[mt][nt], aRb[mt][0], aRb[mt][1], aRb[mt][2], aRb[mt][3],
                             bRs[nt][0], bRs[nt][1]);
                }
        }
        if (more) {
            float* An = sm1 + (buf ^ 1) * P1_STRIDE;
            float* Asn = An + P1_ABUF;
            float* Bn = Asn + P1_ABUF;
            float* Bsn = Bn + P1_BBUF;
            sts4split(&An[lr * AST + lkq],        &Asn[lr * AST + lkq],        na0);
            sts4split(&An[(lr + 64) * AST + lkq], &Asn[(lr + 64) * AST + lkq], na1);
            sts4split(&Bn[lr * AST + lkq],        &Bsn[lr * AST + lkq],        nb0);
        }
        __syncthreads();
        buf ^= 1;
    }

    // Epilogue: add bias, store to g_gates[t][n][b]
#pragma unroll
    for (int nt = 0; nt < 2; nt++) {
        const int n = n0 + wn * 16 + nt * 8 + 2 * q4;
        const float bias0 = b_ih[n] + b_hh[n];
        const float bias1 = b_ih[n + 1] + b_hh[n + 1];
#pragma unroll
        for (int mt = 0; mt < 4; mt++) {
            const int m = m0 + wm * 64 + mt * 16 + g8;
            const size_t idx = (size_t)(m >> 5) * (G4 * BATCH)
                             + (size_t)n * BATCH + (m & 31);
            g_gates[idx]             = acc[mt][nt][0] + bias0;
            g_gates[idx + BATCH]     = acc[mt][nt][1] + bias1;
            g_gates[idx + 8]         = acc[mt][nt][2] + bias0;
            g_gates[idx + 8 + BATCH] = acc[mt][nt][3] + bias1;
        }
    }
}

// ---------------------------------------------------------------------------
// Software grid barrier (128 CTAs co-resident, 1 per SM)
// ---------------------------------------------------------------------------
__device__ __forceinline__ void grid_sync()
{
    __syncthreads();
    if (threadIdx.x == 0) {
        const unsigned gen = *((volatile unsigned*)&g_bar_gen);
        __threadfence();
        const unsigned old = atomicAdd(&g_bar_count, 1u);
        if (old == (unsigned)gridDim.x - 1u) {
            atomicExch(&g_bar_count, 0u);
            __threadfence();
            atomicAdd(&g_bar_gen, 1u);
        } else {
            while (*((volatile unsigned*)&g_bar_gen) == gen) { }
        }
    }
    __syncthreads();
}

// ---------------------------------------------------------------------------
// Phase 2: persistent recurrent scan, 3xTF32 mma.
// CTA owns h-units [j0, j0+4) -> 16 gate rows (M=16).  N=32 batch, K=512.
// W_hh fragments (big+small) live in registers for all 1024 steps.
// B fragments (h) loaded straight from g_h with __ldcg, split in registers.
// 8-way K-split across warps, fp32 partials reduced via smem, activations by
// 128 threads, software grid barrier per step.
// ---------------------------------------------------------------------------
#define HST 40

__global__ __launch_bounds__(256, 1) void lstm_scan_kernel(
    const float* __restrict__ h0,
    const float* __restrict__ c0,
    const float* __restrict__ Whh,   // [2048, 512]
    float* __restrict__ out)         // [T,B,H] ++ h_f[B,H] ++ c_f[B,H]
{
    __shared__ float red[8 * 16 * HST];   // [kslice][row rr][b]
    __shared__ float hn[4 * 32];          // h_new staging

    const int tid  = threadIdx.x;
    const int w    = tid >> 5;
    const int lane = tid & 31;
    const int g8   = lane >> 2;
    const int q4   = lane & 3;
    const int j0   = blockIdx.x << 2;

    // Resident W_hh fragments (big + small): warp w owns k in [w*64, w*64+64).
    // C row rr = g*4+u  ->  W_hh row g*512 + j0 + u.
    unsigned aFb[8][4], aFs[8][4];
    {
        const int r0 = g8, r1 = g8 + 8;
        const int row0 = (r0 >> 2) * HDIM + j0 + (r0 & 3);
        const int row1 = (r1 >> 2) * HDIM + j0 + (r1 & 3);
#pragma unroll
        for (int kt = 0; kt < 8; kt++) {
            const int col = w * 64 + kt * 8 + q4;
            const float w0 = Whh[(size_t)row0 * HDIM + col];
            const float w1 = Whh[(size_t)row1 * HDIM + col];
            const float w2 = Whh[(size_t)row0 * HDIM + col + 4];
            const float w3 = Whh[(size_t)row1 * HDIM + col + 4];
            aFb[kt][0] = f2tf(w0); aFs[kt][0] = f2tf(w0 - __uint_as_float(aFb[kt][0]));
            aFb[kt][1] = f2tf(w1); aFs[kt][1] = f2tf(w1 - __uint_as_float(aFb[kt][1]));
            aFb[kt][2] = f2tf(w2); aFs[kt][2] = f2tf(w2 - __uint_as_float(aFb[kt][2]));
            aFb[kt][3] = f2tf(w3); aFs[kt][3] = f2tf(w3 - __uint_as_float(aFb[kt][3]));
        }
    }

    const int bb = tid & 31;
    const int uu = (tid >> 5) & 3;
    float c_reg = (tid < 128) ? c0[bb * HDIM + j0 + uu] : 0.f;

    float* hf  = out + (size_t)T_STEPS * BATCH * HDIM;
    float* cfp = hf + BATCH * HDIM;

    for (int t = 0; t < T_STEPS; t++) {
        // prefetch gates_x for this step (tid < 128)
        float gxv[4] = {0.f, 0.f, 0.f, 0.f};
        if (tid < 128) {
#pragma unroll
            for (int g = 0; g < 4; g++)
                gxv[g] = g_gates[(size_t)t * (G4 * BATCH)
                                 + (size_t)(g * HDIM + j0 + uu) * BATCH + bb];
        }

        // ---- mma: C[16][32] partial over this warp's 64 k ----
        float cf4[4][4];
#pragma unroll
        for (int nt = 0; nt < 4; nt++)
#pragma unroll
            for (int e = 0; e < 4; e++) cf4[nt][e] = 0.f;

        const float* hsrc = g_h[t & 1];
#pragma unroll
        for (int kt = 0; kt < 8; kt++) {
            const int k0 = w * 64 + kt * 8 + q4;   // b0 k-index; b1 is k0+4
            float v0[4], v1[4];
#pragma unroll
            for (int nt = 0; nt < 4; nt++) {
                const int b = nt * 8 + g8;
                if (t == 0) {
                    v0[nt] = h0[b * HDIM + k0];
                    v1[nt] = h0[b * HDIM + k0 + 4];
                } else {
                    v0[nt] = __ldcg(hsrc + k0 * 32 + b);
                    v1[nt] = __ldcg(hsrc + (k0 + 4) * 32 + b);
                }
            }
#pragma unroll
            for (int nt = 0; nt < 4; nt++) {
                const unsigned b0b = f2tf(v0[nt]);
                const unsigned b1b = f2tf(v1[nt]);
                const unsigned b0s = f2tf(v0[nt] - __uint_as_float(b0b));
                const unsigned b1s = f2tf(v1[nt] - __uint_as_float(b1b));
                mma_tf32(cf4[nt], aFb[kt][0], aFb[kt][1], aFb[kt][2], aFb[kt][3], b0b, b1b);
                mma_tf32(cf4[nt], aFs[kt][0], aFs[kt][1], aFs[kt][2], aFs[kt][3], b0b, b1b);
                mma_tf32(cf4[nt], aFb[kt][0], aFb[kt][1], aFb[kt][2], aFb[kt][3], b0s, b1s);
            }
        }

        // ---- store partials to red[w][rr][b] ----
        float* rw = red + w * 16 * HST;
#pragma unroll
        for (int nt = 0; nt < 4; nt++) {
            const int colb = nt * 8 + 2 * q4;
            rw[g8 * HST + colb]           = cf4[nt][0];
            rw[g8 * HST + colb + 1]       = cf4[nt][1];
            rw[(g8 + 8) * HST + colb]     = cf4[nt][2];
            rw[(g8 + 8) * HST + colb + 1] = cf4[nt][3];
        }
        __syncthreads();

        // ---- reduce + activations (tid < 128: one (b, u) cell) ----
        if (tid < 128) {
            float s[4];
#pragma unroll
            for (int g = 0; g < 4; g++) {
                const int rr = g * 4 + uu;
                float v = gxv[g];
#pragma unroll
                for (int kk = 0; kk < 8; kk++)
                    v += red[kk * 16 * HST + rr * HST + bb];
                s[g] = v;
            }
            const float ig = 1.f / (1.f + expf(-s[0]));
            const float fg = 1.f / (1.f + expf(-s[1]));
            const float gg = tanhf(s[2]);
            const float og = 1.f / (1.f + expf(-s[3]));
            c_reg = fg * c_reg + ig * gg;
            const float hnew = og * tanhf(c_reg);

            g_h[(t + 1) & 1][(j0 + uu) * 32 + bb] = hnew;   // coalesced
            hn[uu * 32 + bb] = hnew;
            if (t == T_STEPS - 1) {
                hf[bb * HDIM + j0 + uu]  = hnew;
                cfp[bb * HDIM + j0 + uu] = c_reg;
            }
        }
        __syncthreads();

        // ---- output store: out[t][b][j0..j0+3] ----
        if (tid < 32) {
            const float4 o4 = make_float4(hn[tid], hn[32 + tid],
                                          hn[64 + tid], hn[96 + tid]);
            *(float4*)(out + (size_t)t * (BATCH * HDIM) + tid * HDIM + j0) = o4;
        }

        grid_sync();
    }
}

// ---------------------------------------------------------------------------
extern "C" void kernel_launch(void* const* d_in, const int* in_sizes, int n_in,
                              void* d_out, int out_size)
{
    const float* input = (const float*)d_in[0];   // [T,B,I]
    const float* h0    = (const float*)d_in[1];   // [B,H]
    const float* c0    = (const float*)d_in[2];   // [B,H]
    const float* W_ih  = (const float*)d_in[3];   // [4H,I]
    const float* W_hh  = (const float*)d_in[4];   // [4H,H]
    const float* b_ih  = (const float*)d_in[5];   // [4H]
    const float* b_hh  = (const float*)d_in[6];   // [4H]
    float* out = (float*)d_out;

    const int smem1 = 2 * P1_STRIDE * (int)sizeof(float);   // 61440 B
    cudaFuncSetAttribute(gemm_x_kernel,
                         cudaFuncAttributeMaxDynamicSharedMemorySize, smem1);
    dim3 g1(G4 / 64, (T_STEPS * BATCH) / 128);    // (32, 256)
    gemm_x_kernel<<<g1, 256, smem1>>>(input, W_ih, b_ih, b_hh);

    lstm_scan_kernel<<<NCTA, 256>>>(h0, c0, W_hh, out);
}

// round 5
// speedup vs baseline: 1.4011x; 1.0840x over previous
#include <cuda_runtime.h>
#include <cstdint>

// Problem constants
#define T_STEPS 1024
#define BATCH   32
#define INDIM   512
#define HDIM    512
#define G4      2048            // 4*H
#define NCTA    128             // persistent scan CTAs

// Scratch: gates_x stored as [t][n][b] (n-major, b-minor)
__device__ float g_gates[(size_t)T_STEPS * G4 * BATCH];  // 256 MB
// Double-buffered recurrent hidden state, layout [k*32 + b] (full fp32)
__device__ float g_h[2][HDIM * BATCH];
// Software grid barrier state
__device__ unsigned g_bar_count = 0;
__device__ unsigned g_bar_gen   = 0;

// ---------------------------------------------------------------------------
// tf32 helpers (3xTF32 scheme: x*y ~= xb*yb + xs*yb + xb*ys)
// ---------------------------------------------------------------------------
__device__ __forceinline__ unsigned f2tf(float x) {
    unsigned r;
    asm("cvt.rna.tf32.f32 %0, %1;" : "=r"(r) : "f"(x));
    return r;
}
__device__ __forceinline__ float f2tf_f(float x) { return __uint_as_float(f2tf(x)); }

__device__ __forceinline__ void mma_tf32(float c[4],
                                         unsigned a0, unsigned a1, unsigned a2, unsigned a3,
                                         unsigned b0, unsigned b1) {
    asm volatile(
        "mma.sync.aligned.m16n8k8.row.col.f32.tf32.tf32.f32 "
        "{%0,%1,%2,%3}, {%4,%5,%6,%7}, {%8,%9}, {%0,%1,%2,%3};"
        : "+f"(c[0]), "+f"(c[1]), "+f"(c[2]), "+f"(c[3])
        : "r"(a0), "r"(a1), "r"(a2), "r"(a3), "r"(b0), "r"(b1));
}

// ---------------------------------------------------------------------------
// Phase 1: gates_x GEMM (3xTF32).  (unchanged from passing R3)
// ---------------------------------------------------------------------------
#define AST 20
#define P1_ABUF (128 * AST)
#define P1_BBUF (64 * AST)
#define P1_STRIDE (2 * P1_ABUF + 2 * P1_BBUF)

__device__ __forceinline__ void sts4split(float* pb, float* ps, float4 v) {
    const float bx = f2tf_f(v.x), by = f2tf_f(v.y);
    const float bz = f2tf_f(v.z), bw = f2tf_f(v.w);
    *(float4*)pb = make_float4(bx, by, bz, bw);
    *(float4*)ps = make_float4(f2tf_f(v.x - bx), f2tf_f(v.y - by),
                               f2tf_f(v.z - bz), f2tf_f(v.w - bw));
}

__global__ __launch_bounds__(256) void gemm_x_kernel(
    const float* __restrict__ A,     // input  [32768, 512]
    const float* __restrict__ W,     // W_ih   [2048, 512]
    const float* __restrict__ b_ih,
    const float* __restrict__ b_hh)
{
    extern __shared__ float sm1[];

    const int tid  = threadIdx.x;
    const int w    = tid >> 5;
    const int lane = tid & 31;
    const int g8   = lane >> 2;
    const int q4   = lane & 3;
    const int wm   = w >> 2;
    const int wn   = w & 3;
    const int m0   = blockIdx.y << 7;
    const int n0   = blockIdx.x << 6;

    const int lr  = tid >> 2;
    const int lkq = (tid & 3) << 2;
    const float* Ap = A + (size_t)(m0 + lr) * INDIM + lkq;
    const float* Wp = W + (size_t)(n0 + lr) * INDIM + lkq;

    float acc[4][2][4];
#pragma unroll
    for (int mt = 0; mt < 4; mt++)
#pragma unroll
        for (int nt = 0; nt < 2; nt++)
#pragma unroll
            for (int e = 0; e < 4; e++) acc[mt][nt][e] = 0.f;

    {
        float* Ab = sm1;                float* As = sm1 + P1_ABUF;
        float* Bb = As + P1_ABUF;       float* Bs = Bb + P1_BBUF;
        sts4split(&Ab[lr * AST + lkq],        &As[lr * AST + lkq],        *(const float4*)Ap);
        sts4split(&Ab[(lr + 64) * AST + lkq], &As[(lr + 64) * AST + lkq], *(const float4*)(Ap + 64 * INDIM));
        sts4split(&Bb[lr * AST + lkq],        &Bs[lr * AST + lkq],        *(const float4*)Wp);
    }
    __syncthreads();

    int buf = 0;
    for (int kc = 0; kc < INDIM; kc += 16) {
        const bool more = (kc + 16 < INDIM);
        float4 na0, na1, nb0;
        if (more) {
            na0 = *(const float4*)(Ap + kc + 16);
            na1 = *(const float4*)(Ap + 64 * INDIM + kc + 16);
            nb0 = *(const float4*)(Wp + kc + 16);
        }
        const float* Ab = sm1 + buf * P1_STRIDE;
        const float* As = Ab + P1_ABUF;
        const float* Bb = As + P1_ABUF;
        const float* Bs = Bb + P1_BBUF;
#pragma unroll
        for (int kt = 0; kt < 16; kt += 8) {
            unsigned aRb[4][4], aRs[4][4], bRb[2][2], bRs[2][2];
#pragma unroll
            for (int mt = 0; mt < 4; mt++) {
                const int off = (wm * 64 + mt * 16 + g8) * AST + kt + q4;
                aRb[mt][0] = __float_as_uint(Ab[off]);
                aRb[mt][1] = __float_as_uint(Ab[off + 8 * AST]);
                aRb[mt][2] = __float_as_uint(Ab[off + 4]);
                aRb[mt][3] = __float_as_uint(Ab[off + 8 * AST + 4]);
                aRs[mt][0] = __float_as_uint(As[off]);
                aRs[mt][1] = __float_as_uint(As[off + 8 * AST]);
                aRs[mt][2] = __float_as_uint(As[off + 4]);
                aRs[mt][3] = __float_as_uint(As[off + 8 * AST + 4]);
            }
#pragma unroll
            for (int nt = 0; nt < 2; nt++) {
                const int off = (wn * 16 + nt * 8 + g8) * AST + kt + q4;
                bRb[nt][0] = __float_as_uint(Bb[off]);
                bRb[nt][1] = __float_as_uint(Bb[off + 4]);
                bRs[nt][0] = __float_as_uint(Bs[off]);
                bRs[nt][1] = __float_as_uint(Bs[off + 4]);
            }
#pragma unroll
            for (int mt = 0; mt < 4; mt++)
#pragma unroll
                for (int nt = 0; nt < 2; nt++) {
                    mma_tf32(acc[mt][nt], aRb[mt][0], aRb[mt][1], aRb[mt][2], aRb[mt][3],
                             bRb[nt][0], bRb[nt][1]);
                    mma_tf32(acc[mt][nt], aRs[mt][0], aRs[mt][1], aRs[mt][2], aRs[mt][3],
                             bRb[nt][0], bRb[nt][1]);
                    mma_tf32(acc[mt][nt], aRb[mt][0], aRb[mt][1], aRb[mt][2], aRb[mt][3],
                             bRs[nt][0], bRs[nt][1]);
                }
        }
        if (more) {
            float* An  = sm1 + (buf ^ 1) * P1_STRIDE;
            float* Asn = An + P1_ABUF;
            float* Bn  = Asn + P1_ABUF;
            float* Bsn = Bn + P1_BBUF;
            sts4split(&An[lr * AST + lkq],        &Asn[lr * AST + lkq],        na0);
            sts4split(&An[(lr + 64) * AST + lkq], &Asn[(lr + 64) * AST + lkq], na1);
            sts4split(&Bn[lr * AST + lkq],        &Bsn[lr * AST + lkq],        nb0);
        }
        __syncthreads();
        buf ^= 1;
    }

#pragma unroll
    for (int nt = 0; nt < 2; nt++) {
        const int n = n0 + wn * 16 + nt * 8 + 2 * q4;
        const float bias0 = b_ih[n] + b_hh[n];
        const float bias1 = b_ih[n + 1] + b_hh[n + 1];
#pragma unroll
        for (int mt = 0; mt < 4; mt++) {
            const int m = m0 + wm * 64 + mt * 16 + g8;
            const size_t idx = (size_t)(m >> 5) * (G4 * BATCH)
                             + (size_t)n * BATCH + (m & 31);
            g_gates[idx]             = acc[mt][nt][0] + bias0;
            g_gates[idx + BATCH]     = acc[mt][nt][1] + bias1;
            g_gates[idx + 8]         = acc[mt][nt][2] + bias0;
            g_gates[idx + 8 + BATCH] = acc[mt][nt][3] + bias1;
        }
    }
}

// ---------------------------------------------------------------------------
// Software grid barrier (128 CTAs co-resident, 1 per SM)
// ---------------------------------------------------------------------------
__device__ __forceinline__ void grid_sync()
{
    __syncthreads();
    if (threadIdx.x == 0) {
        const unsigned gen = *((volatile unsigned*)&g_bar_gen);
        __threadfence();
        const unsigned old = atomicAdd(&g_bar_count, 1u);
        if (old == (unsigned)gridDim.x - 1u) {
            atomicExch(&g_bar_count, 0u);
            __threadfence();
            atomicAdd(&g_bar_gen, 1u);
        } else {
            while (*((volatile unsigned*)&g_bar_gen) == gen) { }
        }
    }
    __syncthreads();
}

// ---------------------------------------------------------------------------
// Phase 2: persistent recurrent scan, 3xTF32 mma.
// CTA owns h-units [j0, j0+4) -> 16 gate rows (M=16).  N=32 batch, K=512.
// W_hh fragments (big+small) register-resident for all 1024 steps.
// Per step: coalesced float4 all-gather of g_h into smem hshT[k][b] (stride
// 40 -> conflict-free fragment LDS), register big/small split, 8-way K-split
// mma, smem reduce, activations, grid barrier.
// ---------------------------------------------------------------------------
#define HST 40

__global__ __launch_bounds__(256, 1) void lstm_scan_kernel(
    const float* __restrict__ h0,
    const float* __restrict__ c0,
    const float* __restrict__ Whh,   // [2048, 512]
    float* __restrict__ out)         // [T,B,H] ++ h_f[B,H] ++ c_f[B,H]
{
    extern __shared__ float sm[];
    float* hshT = sm;                        // [512][40]  h staged, fp32
    float* red  = hshT + HDIM * HST;         // [8][16][40] partials
    float* hn   = red + 8 * 16 * HST;        // [4][32]

    const int tid  = threadIdx.x;
    const int w    = tid >> 5;
    const int lane = tid & 31;
    const int g8   = lane >> 2;
    const int q4   = lane & 3;
    const int j0   = blockIdx.x << 2;

    // Resident W_hh fragments (big + small): warp w owns k in [w*64, w*64+64).
    unsigned aFb[8][4], aFs[8][4];
    {
        const int r0 = g8, r1 = g8 + 8;
        const int row0 = (r0 >> 2) * HDIM + j0 + (r0 & 3);
        const int row1 = (r1 >> 2) * HDIM + j0 + (r1 & 3);
#pragma unroll
        for (int kt = 0; kt < 8; kt++) {
            const int col = w * 64 + kt * 8 + q4;
            const float w0 = Whh[(size_t)row0 * HDIM + col];
            const float w1 = Whh[(size_t)row1 * HDIM + col];
            const float w2 = Whh[(size_t)row0 * HDIM + col + 4];
            const float w3 = Whh[(size_t)row1 * HDIM + col + 4];
            aFb[kt][0] = f2tf(w0); aFs[kt][0] = f2tf(w0 - __uint_as_float(aFb[kt][0]));
            aFb[kt][1] = f2tf(w1); aFs[kt][1] = f2tf(w1 - __uint_as_float(aFb[kt][1]));
            aFb[kt][2] = f2tf(w2); aFs[kt][2] = f2tf(w2 - __uint_as_float(aFb[kt][2]));
            aFb[kt][3] = f2tf(w3); aFs[kt][3] = f2tf(w3 - __uint_as_float(aFb[kt][3]));
        }
    }

    const int bb = tid & 31;
    const int uu = (tid >> 5) & 3;
    float c_reg = (tid < 128) ? c0[bb * HDIM + j0 + uu] : 0.f;

    // Prefill g_h[0] with h0 in scan layout [k][b]: CTA owns k = j0..j0+3
    if (tid < 128)
        g_h[0][(j0 + uu) * 32 + bb] = h0[bb * HDIM + j0 + uu];
    grid_sync();

    float* hf  = out + (size_t)T_STEPS * BATCH * HDIM;
    float* cfp = hf + BATCH * HDIM;

    for (int t = 0; t < T_STEPS; t++) {
        // ---- coalesced all-gather of h into hshT [k][b] ----
        const float4* src = (const float4*)g_h[t & 1];
#pragma unroll
        for (int i = 0; i < 16; i++) {
            const int f = tid + i * 256;                 // float4 index, 0..4095
            const float4 v = __ldcg(src + f);
            *(float4*)&hshT[(f >> 3) * HST + ((f & 7) << 2)] = v;
        }

        // prefetch gates_x for this step (independent of h)
        float gxv[4] = {0.f, 0.f, 0.f, 0.f};
        if (tid < 128) {
#pragma unroll
            for (int g = 0; g < 4; g++)
                gxv[g] = __ldcg(&g_gates[(size_t)t * (G4 * BATCH)
                                + (size_t)(g * HDIM + j0 + uu) * BATCH + bb]);
        }
        __syncthreads();

        // ---- mma: C[16][32] partial over this warp's 64 k ----
        float cf4[4][4];
#pragma unroll
        for (int nt = 0; nt < 4; nt++)
#pragma unroll
            for (int e = 0; e < 4; e++) cf4[nt][e] = 0.f;

#pragma unroll
        for (int kt = 0; kt < 8; kt++) {
            const float* hb = hshT + (w * 64 + kt * 8 + q4) * HST;
#pragma unroll
            for (int nt = 0; nt < 4; nt++) {
                const int b = nt * 8 + g8;
                const float v0 = hb[b];
                const float v1 = hb[4 * HST + b];
                const unsigned b0b = f2tf(v0);
                const unsigned b1b = f2tf(v1);
                const unsigned b0s = f2tf(v0 - __uint_as_float(b0b));
                const unsigned b1s = f2tf(v1 - __uint_as_float(b1b));
                mma_tf32(cf4[nt], aFb[kt][0], aFb[kt][1], aFb[kt][2], aFb[kt][3], b0b, b1b);
                mma_tf32(cf4[nt], aFs[kt][0], aFs[kt][1], aFs[kt][2], aFs[kt][3], b0b, b1b);
                mma_tf32(cf4[nt], aFb[kt][0], aFb[kt][1], aFb[kt][2], aFb[kt][3], b0s, b1s);
            }
        }

        // ---- store partials to red[w][rr][b] ----
        float* rw = red + w * 16 * HST;
#pragma unroll
        for (int nt = 0; nt < 4; nt++) {
            const int colb = nt * 8 + 2 * q4;
            rw[g8 * HST + colb]           = cf4[nt][0];
            rw[g8 * HST + colb + 1]       = cf4[nt][1];
            rw[(g8 + 8) * HST + colb]     = cf4[nt][2];
            rw[(g8 + 8) * HST + colb + 1] = cf4[nt][3];
        }
        __syncthreads();

        // ---- reduce + activations (tid < 128: one (b, u) cell) ----
        if (tid < 128) {
            float s[4];
#pragma unroll
            for (int g = 0; g < 4; g++) {
                const int rr = g * 4 + uu;
                float v = gxv[g];
#pragma unroll
                for (int kk = 0; kk < 8; kk++)
                    v += red[kk * 16 * HST + rr * HST + bb];
                s[g] = v;
            }
            const float ig = 1.f / (1.f + expf(-s[0]));
            const float fg = 1.f / (1.f + expf(-s[1]));
            const float gg = tanhf(s[2]);
            const float og = 1.f / (1.f + expf(-s[3]));
            c_reg = fg * c_reg + ig * gg;
            const float hnew = og * tanhf(c_reg);

            g_h[(t + 1) & 1][(j0 + uu) * 32 + bb] = hnew;   // coalesced
            hn[uu * 32 + bb] = hnew;
            if (t == T_STEPS - 1) {
                hf[bb * HDIM + j0 + uu]  = hnew;
                cfp[bb * HDIM + j0 + uu] = c_reg;
            }
        }
        __syncthreads();

        // ---- output store: out[t][b][j0..j0+3] ----
        if (tid < 32) {
            const float4 o4 = make_float4(hn[tid], hn[32 + tid],
                                          hn[64 + tid], hn[96 + tid]);
            *(float4*)(out + (size_t)t * (BATCH * HDIM) + tid * HDIM + j0) = o4;
        }

        grid_sync();
    }
}

// ---------------------------------------------------------------------------
extern "C" void kernel_launch(void* const* d_in, const int* in_sizes, int n_in,
                              void* d_out, int out_size)
{
    const float* input = (const float*)d_in[0];   // [T,B,I]
    const float* h0    = (const float*)d_in[1];   // [B,H]
    const float* c0    = (const float*)d_in[2];   // [B,H]
    const float* W_ih  = (const float*)d_in[3];   // [4H,I]
    const float* W_hh  = (const float*)d_in[4];   // [4H,H]
    const float* b_ih  = (const float*)d_in[5];   // [4H]
    const float* b_hh  = (const float*)d_in[6];   // [4H]
    float* out = (float*)d_out;

    const int smem1 = 2 * P1_STRIDE * (int)sizeof(float);   // 61440 B
    cudaFuncSetAttribute(gemm_x_kernel,
                         cudaFuncAttributeMaxDynamicSharedMemorySize, smem1);
    dim3 g1(G4 / 64, (T_STEPS * BATCH) / 128);    // (32, 256)
    gemm_x_kernel<<<g1, 256, smem1>>>(input, W_ih, b_ih, b_hh);

    const int smem2 = (HDIM * HST + 8 * 16 * HST + 4 * 32) * (int)sizeof(float);
    cudaFuncSetAttribute(lstm_scan_kernel,
                         cudaFuncAttributeMaxDynamicSharedMemorySize, smem2);
    lstm_scan_kernel<<<NCTA, 256, smem2>>>(h0, c0, W_hh, out);
}